// round 2
// baseline (speedup 1.0000x reference)
#include <cuda_runtime.h>

// ============================================================================
// Sparse e3nn tensor product, uvu mode.
// irreps1 = 128x0e+128x1o+128x2e (x1: [Z,1152]), irreps2 = 1x0e+1x1o+1x2e.
// 83-entry hardcoded sparsity pattern; coefficient VALUES computed on device
// each launch by a fast fp32 init kernel (exact port of reference su2_cg +
// real-basis transform). Main kernel stages rows via float4 <-> shared memory.
// ============================================================================

#define NE 83
#define NT 11

__device__ float cg_coef[NE];

__constant__ int TL1[NT] = {0,0,0,1,1,1,1,2,2,2,2};
__constant__ int TL2[NT] = {0,1,2,0,1,1,2,0,1,2,2};
__constant__ int TL3[NT] = {0,1,2,1,0,2,1,2,1,0,2};
__constant__ float TALPHA[NT] = {
  0.57735026918962584f, 0.86602540378443865f, 1.11803398874989485f,
  0.86602540378443865f, 0.57735026918962584f, 1.11803398874989485f,
  0.86602540378443865f, 1.11803398874989485f, 0.86602540378443865f,
  0.57735026918962584f, 1.11803398874989485f};

__constant__ unsigned char ENT_T[NE] = {
  0,
  1,1,1,
  2,2,2,2,2,
  3,3,3,
  4,4,4,
  5,5,5,5,5,5,5,5,5,5,5,
  6,6,6,6,6,6,6,6,6,6,6,
  7,7,7,7,7,
  8,8,8,8,8,8,8,8,8,8,8,
  9,9,9,9,9,
  10,10,10,10,10,10,10,10,10,10,10,10,10,10,10,10,10,10,10,10,10,10,10,10,10};
__constant__ unsigned char ENT_I[NE] = {
  0,
  0,0,0,
  0,0,0,0,0,
  0,1,2,
  0,1,2,
  1,1,1,2,0,2,0,2,0,2,0,
  1,1,1,2,0,2,0,2,0,2,0,
  0,1,2,3,4,
  2,2,2,3,1,3,1,4,4,0,0,
  0,1,2,3,4,
  2,2,2,3,1,2,2,4,0,3,1,3,1,3,1,3,1,3,1,4,0,4,0,4,0};
__constant__ unsigned char ENT_J[NE] = {
  0,
  0,1,2,
  0,1,2,3,4,
  0,0,0,
  0,1,2,
  1,2,0,1,1,2,0,2,0,0,2,
  2,3,1,2,2,3,1,4,4,0,0,
  0,0,0,0,0,
  1,2,0,1,1,2,0,2,0,2,0,
  0,1,2,3,4,
  2,3,1,2,2,4,0,2,2,3,1,3,1,1,3,4,4,0,0,3,3,1,1,4,0};
__constant__ unsigned char ENT_K[NE] = {
  0,
  0,1,2,
  0,1,2,3,4,
  0,1,2,
  0,0,0,
  2,3,1,3,1,2,2,4,4,0,0,
  1,2,0,2,0,1,1,2,0,0,2,
  0,1,2,3,4,
  1,2,0,2,0,1,1,2,0,0,2,
  0,0,0,0,0,
  2,3,1,3,1,4,0,4,0,2,2,4,4,0,0,3,1,1,3,3,1,1,3,2,2};

// ---------------------------------------------------------------------------
// fp32 init kernel (exact structure of reference; fp32 is plenty for 1e-3 tol)
// ---------------------------------------------------------------------------
__device__ __forceinline__ float ffact(int n) {
  float r = 1.0f;
  for (int i = 2; i <= n; ++i) r *= (float)i;
  return r;
}

__device__ float su2cg_f(int j1,int m1,int j2,int m2,int j3,int m3) {
  if (m1 + m2 != m3) return 0.0f;
  int vmin = max(max(-j1+j2+m3, -j1+m1), 0);
  int vmax = min(min(j2+j3+m1, j3-j1+j2), j3+m3);
  float C = sqrtf((2.0f*j3+1.0f)*ffact(j3+j1-j2)*ffact(j3-j1+j2)*ffact(j1+j2-j3)
                  *ffact(j3+m3)*ffact(j3-m3)
                  /(ffact(j1+j2+j3+1)*ffact(j1-m1)*ffact(j1+m1)*ffact(j2-m2)*ffact(j2+m2)));
  float S = 0.0f;
  for (int v = vmin; v <= vmax; ++v) {
    float s = ((v + j2 + m2) & 1) ? -1.0f : 1.0f;
    S += s * ffact(j2+j3+m1-v)*ffact(j1-m1+v)
         /(ffact(v)*ffact(j3-j1+j2-v)*ffact(j3+m3-v)*ffact(v+j1-j2-m3));
  }
  return C * S;
}

__device__ __forceinline__ void qent_f(int l, int r, int c, float* qr, float* qi) {
  const float inv2 = 0.70710678118654752f;
  float re = 0.0f, im = 0.0f;
  int m = r - l;
  if (m < 0) {
    if (c == l - m) re = inv2;
    if (c == l + m) im = -inv2;
  } else if (m == 0) {
    if (c == l) re = 1.0f;
  } else {
    float s = (m & 1) ? -1.0f : 1.0f;
    if (c == l + m) re = s * inv2;
    if (c == l - m) im = s * inv2;
  }
  if (l == 1) { float t0 = re; re = im; im = -t0; }
  else if (l == 2) { re = -re; im = -im; }
  *qr = re; *qi = im;
}

__global__ void init_cg_kernel() {
  int t  = blockIdx.x;
  int l1 = TL1[t], l2 = TL2[t], l3 = TL3[t];
  int d1 = 2*l1+1, d2 = 2*l2+1, d3 = 2*l3+1;
  int n  = d1*d2*d3;
  __shared__ float cgc[125];
  __shared__ float cre[125];
  __shared__ float wsum[4];
  __shared__ float snrm;
  int tid = threadIdx.x;

  for (int e = tid; e < n; e += blockDim.x) {
    int i  = e/(d2*d3);
    int k  = (e/d3)%d2;
    int nn = e%d3;
    cgc[e] = su2cg_f(l1, i-l1, l2, k-l2, l3, nn-l3);
  }
  __syncthreads();

  for (int e = tid; e < n; e += blockDim.x) {
    int j = e/(d2*d3);
    int l = (e/d3)%d2;
    int m = e%d3;
    float acc = 0.0f;
    for (int i = 0; i < d1; ++i) {
      for (int k = 0; k < d2; ++k) {
        int nn = (i-l1) + (k-l2) + l3;
        if (nn < 0 || nn >= d3) continue;
        float cv = cgc[(i*d2+k)*d3+nn];
        if (cv == 0.0f) continue;
        float q1r,q1i,q2r,q2i,q3r,q3i;
        qent_f(l1, i,  j, &q1r, &q1i);
        if (q1r == 0.0f && q1i == 0.0f) continue;
        qent_f(l2, k,  l, &q2r, &q2i);
        if (q2r == 0.0f && q2i == 0.0f) continue;
        qent_f(l3, nn, m, &q3r, &q3i);
        float tr = q1r*q2r - q1i*q2i;
        float ti = q1r*q2i + q1i*q2r;
        acc += cv * (tr*q3r + ti*q3i);
      }
    }
    cre[e] = acc;
  }
  __syncthreads();

  // parallel Frobenius-norm reduction
  {
    float v = 0.0f;
    for (int e = tid; e < n; e += blockDim.x) v += cre[e]*cre[e];
    #pragma unroll
    for (int off = 16; off > 0; off >>= 1)
      v += __shfl_down_sync(0xffffffffu, v, off);
    if ((tid & 31) == 0) wsum[tid >> 5] = v;
    __syncthreads();
    if (tid == 0) {
      float s = wsum[0] + wsum[1] + wsum[2] + wsum[3];
      snrm = rsqrtf(s);
    }
    __syncthreads();
  }

  float scale = snrm * TALPHA[t];
  for (int e = tid; e < NE; e += blockDim.x) {
    if (ENT_T[e] != t) continue;
    int idx = ((int)ENT_I[e]*d2 + (int)ENT_J[e])*d3 + (int)ENT_K[e];
    cg_coef[e] = cre[idx] * scale;
  }
}

// ---------------------------------------------------------------------------
// Main kernel: 256 threads, 2 rows per block, float4-staged I/O via smem.
// ---------------------------------------------------------------------------
__global__ __launch_bounds__(256)
void tp_kernel(const float* __restrict__ X1, const float* __restrict__ X2,
               const float* __restrict__ W, float* __restrict__ OUT, int Z)
{
  __shared__ float s[2*1152];      // staged x1, then reused for output
  __shared__ float sx2[2*9];
  __shared__ float g[NE];

  int tid  = threadIdx.x;
  int half = tid >> 7;
  int u    = tid & 127;
  int z0   = blockIdx.x * 2;
  int nrow = Z - z0; if (nrow > 2) nrow = 2;
  int nf4  = nrow * 288;

  if (tid < NE) g[tid] = cg_coef[tid];
  if (tid < nrow * 9) sx2[tid] = X2[(long long)z0 * 9 + tid];

  {
    const float4* __restrict__ src = (const float4*)(X1 + (long long)z0 * 1152);
    float4* dst = (float4*)s;
    #pragma unroll
    for (int i = tid; i < nf4; i += 256) dst[i] = src[i];
  }
  __syncthreads();

  float o0=0.f,o1=0.f,o2=0.f,o3=0.f,o4=0.f,o5=0.f,o6=0.f,o7=0.f,o8=0.f;
  bool active = (half < nrow);

  if (active) {
    const float* sr = s + half * 1152;
    float xx0 = sr[u];
    float xx1 = sr[128 + 3*u    ];
    float xx2 = sr[128 + 3*u + 1];
    float xx3 = sr[128 + 3*u + 2];
    float xx4 = sr[512 + 5*u    ];
    float xx5 = sr[512 + 5*u + 1];
    float xx6 = sr[512 + 5*u + 2];
    float xx7 = sr[512 + 5*u + 3];
    float xx8 = sr[512 + 5*u + 4];

    const float* yr = sx2 + half * 9;
    float y0 = yr[0], y1 = yr[1], y2 = yr[2], y3 = yr[3], y4 = yr[4];
    float y5 = yr[5], y6 = yr[6], y7 = yr[7], y8 = yr[8];

    float wv0  = W[          u];
    float wv1  = W[ 128 +    u];
    float wv2  = W[ 256 +    u];
    float wv3  = W[ 384 +    u];
    float wv4  = W[ 512 +    u];
    float wv5  = W[ 640 +    u];
    float wv6  = W[ 768 +    u];
    float wv7  = W[ 896 +    u];
    float wv8  = W[1024 +    u];
    float wv9  = W[1152 +    u];
    float wv10 = W[1280 +    u];

    // precomputed weight*y products (35)
    float w0y0 = wv0*y0;
    float w1y1 = wv1*y1, w1y2 = wv1*y2, w1y3 = wv1*y3;
    float w2y4 = wv2*y4, w2y5 = wv2*y5, w2y6 = wv2*y6, w2y7 = wv2*y7, w2y8 = wv2*y8;
    float w3y0 = wv3*y0;
    float w4y1 = wv4*y1, w4y2 = wv4*y2, w4y3 = wv4*y3;
    float w5y1 = wv5*y1, w5y2 = wv5*y2, w5y3 = wv5*y3;
    float w6y4 = wv6*y4, w6y5 = wv6*y5, w6y6 = wv6*y6, w6y7 = wv6*y7, w6y8 = wv6*y8;
    float w7y0 = wv7*y0;
    float w8y1 = wv8*y1, w8y2 = wv8*y2, w8y3 = wv8*y3;
    float w9y4 = wv9*y4, w9y5 = wv9*y5, w9y6 = wv9*y6, w9y7 = wv9*y7, w9y8 = wv9*y8;
    float w10y4 = wv10*y4, w10y5 = wv10*y5, w10y6 = wv10*y6, w10y7 = wv10*y7, w10y8 = wv10*y8;

#define ACC(e,t,i,j,k) o##k = fmaf(g[e]*xx##i, w##t##y##j, o##k);
    ACC(0,0, 0,0,0)
    ACC(1,1, 0,1,1)  ACC(2,1, 0,2,2)  ACC(3,1, 0,3,3)
    ACC(4,2, 0,4,4)  ACC(5,2, 0,5,5)  ACC(6,2, 0,6,6)  ACC(7,2, 0,7,7)  ACC(8,2, 0,8,8)
    ACC(9,3, 1,0,1)  ACC(10,3, 2,0,2)  ACC(11,3, 3,0,3)
    ACC(12,4, 1,1,0) ACC(13,4, 2,2,0)  ACC(14,4, 3,3,0)
    ACC(15,5, 2,2,6) ACC(16,5, 2,3,7) ACC(17,5, 2,1,5) ACC(18,5, 3,2,7)
    ACC(19,5, 1,2,5) ACC(20,5, 3,3,6) ACC(21,5, 1,1,6) ACC(22,5, 3,3,8)
    ACC(23,5, 1,1,8) ACC(24,5, 3,1,4) ACC(25,5, 1,3,4)
    ACC(26,6, 2,6,2) ACC(27,6, 2,7,3) ACC(28,6, 2,5,1) ACC(29,6, 3,6,3)
    ACC(30,6, 1,6,1) ACC(31,6, 3,7,2) ACC(32,6, 1,5,2) ACC(33,6, 3,8,3)
    ACC(34,6, 1,8,1) ACC(35,6, 3,4,1) ACC(36,6, 1,4,3)
    ACC(37,7, 4,0,4) ACC(38,7, 5,0,5) ACC(39,7, 6,0,6) ACC(40,7, 7,0,7) ACC(41,7, 8,0,8)
    ACC(42,8, 6,2,2) ACC(43,8, 6,3,3) ACC(44,8, 6,1,1) ACC(45,8, 7,2,3)
    ACC(46,8, 5,2,1) ACC(47,8, 7,3,2) ACC(48,8, 5,1,2) ACC(49,8, 8,3,3)
    ACC(50,8, 8,1,1) ACC(51,8, 4,3,1) ACC(52,8, 4,1,3)
    ACC(53,9, 4,4,0) ACC(54,9, 5,5,0) ACC(55,9, 6,6,0) ACC(56,9, 7,7,0) ACC(57,9, 8,8,0)
    ACC(58,10, 6,6,6) ACC(59,10, 6,7,7) ACC(60,10, 6,5,5) ACC(61,10, 7,6,7)
    ACC(62,10, 5,6,5) ACC(63,10, 6,8,8) ACC(64,10, 6,4,4) ACC(65,10, 8,6,8)
    ACC(66,10, 4,6,4) ACC(67,10, 7,7,6) ACC(68,10, 5,5,6) ACC(69,10, 7,7,8)
    ACC(70,10, 5,5,8) ACC(71,10, 7,5,4) ACC(72,10, 5,7,4) ACC(73,10, 7,8,7)
    ACC(74,10, 5,8,5) ACC(75,10, 7,4,5) ACC(76,10, 5,4,7) ACC(77,10, 8,7,7)
    ACC(78,10, 4,7,5) ACC(79,10, 8,5,5) ACC(80,10, 4,5,7) ACC(81,10, 8,8,6)
    ACC(82,10, 4,4,6)
#undef ACC
  }
  __syncthreads();

  if (active) {
    float* sw = s + half * 1152;
    sw[u] = o0;
    sw[128 + 3*u    ] = o1;
    sw[128 + 3*u + 1] = o2;
    sw[128 + 3*u + 2] = o3;
    sw[512 + 5*u    ] = o4;
    sw[512 + 5*u + 1] = o5;
    sw[512 + 5*u + 2] = o6;
    sw[512 + 5*u + 3] = o7;
    sw[512 + 5*u + 4] = o8;
  }
  __syncthreads();

  {
    float4* __restrict__ dst = (float4*)(OUT + (long long)z0 * 1152);
    const float4* src = (const float4*)s;
    #pragma unroll
    for (int i = tid; i < nf4; i += 256) dst[i] = src[i];
  }
}

// ---------------------------------------------------------------------------
extern "C" void kernel_launch(void* const* d_in, const int* in_sizes, int n_in,
                              void* d_out, int out_size)
{
  const float* x1 = (const float*)d_in[0];
  const float* x2 = (const float*)d_in[1];
  const float* w  = (const float*)d_in[2];
  if (n_in >= 3) {
    int iw = -1, imax = -1;
    long long smax = -1;
    for (int i = 0; i < 3; ++i) {
      if (in_sizes[i] == 1408) iw = i;
      if ((long long)in_sizes[i] > smax) { smax = in_sizes[i]; imax = i; }
    }
    if (iw >= 0 && imax >= 0 && iw != imax) {
      int ix2 = 3 - iw - imax;
      x1 = (const float*)d_in[imax];
      x2 = (const float*)d_in[ix2];
      w  = (const float*)d_in[iw];
    }
  }

  int Z = in_sizes[0] > in_sizes[1]
            ? (in_sizes[0] > in_sizes[2] ? in_sizes[0] : in_sizes[2])
            : (in_sizes[1] > in_sizes[2] ? in_sizes[1] : in_sizes[2]);
  Z /= 1152;

  init_cg_kernel<<<NT, 128>>>();
  int grid = (Z + 1) / 2;
  tp_kernel<<<grid, 256>>>(x1, x2, w, (float*)d_out, Z);
}

// round 5
// speedup vs baseline: 1.2570x; 1.2570x over previous
#include <cuda_runtime.h>

// ============================================================================
// Sparse e3nn tensor product, uvu mode.
// irreps1 = 128x0e+128x1o+128x2e (x1: [Z,1152]), irreps2 = 1x0e+1x1o+1x2e.
// 83-entry hardcoded sparsity pattern; coefficient VALUES computed on device
// each launch (fp32 port of reference su2_cg + real basis transform).
// Main kernel: warp-private float4 staging through shared memory, NO block
// barriers in the data path (only __syncwarp).
// ============================================================================

#define NE 83
#define NT 11

__device__ float cg_coef[NE];

__constant__ int TL1[NT] = {0,0,0,1,1,1,1,2,2,2,2};
__constant__ int TL2[NT] = {0,1,2,0,1,1,2,0,1,2,2};
__constant__ int TL3[NT] = {0,1,2,1,0,2,1,2,1,0,2};
__constant__ float TALPHA[NT] = {
  0.57735026918962584f, 0.86602540378443865f, 1.11803398874989485f,
  0.86602540378443865f, 0.57735026918962584f, 1.11803398874989485f,
  0.86602540378443865f, 1.11803398874989485f, 0.86602540378443865f,
  0.57735026918962584f, 1.11803398874989485f};

__constant__ unsigned char ENT_T[NE] = {
  0,
  1,1,1,
  2,2,2,2,2,
  3,3,3,
  4,4,4,
  5,5,5,5,5,5,5,5,5,5,5,
  6,6,6,6,6,6,6,6,6,6,6,
  7,7,7,7,7,
  8,8,8,8,8,8,8,8,8,8,8,
  9,9,9,9,9,
  10,10,10,10,10,10,10,10,10,10,10,10,10,10,10,10,10,10,10,10,10,10,10,10,10};
__constant__ unsigned char ENT_I[NE] = {
  0,
  0,0,0,
  0,0,0,0,0,
  0,1,2,
  0,1,2,
  1,1,1,2,0,2,0,2,0,2,0,
  1,1,1,2,0,2,0,2,0,2,0,
  0,1,2,3,4,
  2,2,2,3,1,3,1,4,4,0,0,
  0,1,2,3,4,
  2,2,2,3,1,2,2,4,0,3,1,3,1,3,1,3,1,3,1,4,0,4,0,4,0};
__constant__ unsigned char ENT_J[NE] = {
  0,
  0,1,2,
  0,1,2,3,4,
  0,0,0,
  0,1,2,
  1,2,0,1,1,2,0,2,0,0,2,
  2,3,1,2,2,3,1,4,4,0,0,
  0,0,0,0,0,
  1,2,0,1,1,2,0,2,0,2,0,
  0,1,2,3,4,
  2,3,1,2,2,4,0,2,2,3,1,3,1,1,3,4,4,0,0,3,3,1,1,4,0};
__constant__ unsigned char ENT_K[NE] = {
  0,
  0,1,2,
  0,1,2,3,4,
  0,1,2,
  0,0,0,
  2,3,1,3,1,2,2,4,4,0,0,
  1,2,0,2,0,1,1,2,0,0,2,
  0,1,2,3,4,
  1,2,0,2,0,1,1,2,0,0,2,
  0,0,0,0,0,
  2,3,1,3,1,4,0,4,0,2,2,4,4,0,0,3,1,1,3,3,1,1,3,2,2};

// ---------------------------------------------------------------------------
// fp32 init kernel (exact structure of reference math)
// ---------------------------------------------------------------------------
__device__ __forceinline__ float ffact(int n) {
  float r = 1.0f;
  for (int i = 2; i <= n; ++i) r *= (float)i;
  return r;
}

__device__ float su2cg_f(int j1,int m1,int j2,int m2,int j3,int m3) {
  if (m1 + m2 != m3) return 0.0f;
  int vmin = max(max(-j1+j2+m3, -j1+m1), 0);
  int vmax = min(min(j2+j3+m1, j3-j1+j2), j3+m3);
  float C = sqrtf((2.0f*j3+1.0f)*ffact(j3+j1-j2)*ffact(j3-j1+j2)*ffact(j1+j2-j3)
                  *ffact(j3+m3)*ffact(j3-m3)
                  /(ffact(j1+j2+j3+1)*ffact(j1-m1)*ffact(j1+m1)*ffact(j2-m2)*ffact(j2+m2)));
  float S = 0.0f;
  for (int v = vmin; v <= vmax; ++v) {
    float s = ((v + j2 + m2) & 1) ? -1.0f : 1.0f;
    S += s * ffact(j2+j3+m1-v)*ffact(j1-m1+v)
         /(ffact(v)*ffact(j3-j1+j2-v)*ffact(j3+m3-v)*ffact(v+j1-j2-m3));
  }
  return C * S;
}

__device__ __forceinline__ void qent_f(int l, int r, int c, float* qr, float* qi) {
  const float inv2 = 0.70710678118654752f;
  float re = 0.0f, im = 0.0f;
  int m = r - l;
  if (m < 0) {
    if (c == l - m) re = inv2;
    if (c == l + m) im = -inv2;
  } else if (m == 0) {
    if (c == l) re = 1.0f;
  } else {
    float s = (m & 1) ? -1.0f : 1.0f;
    if (c == l + m) re = s * inv2;
    if (c == l - m) im = s * inv2;
  }
  if (l == 1) { float t0 = re; re = im; im = -t0; }
  else if (l == 2) { re = -re; im = -im; }
  *qr = re; *qi = im;
}

__global__ void init_cg_kernel() {
  int t  = blockIdx.x;
  int l1 = TL1[t], l2 = TL2[t], l3 = TL3[t];
  int d1 = 2*l1+1, d2 = 2*l2+1, d3 = 2*l3+1;
  int n  = d1*d2*d3;
  __shared__ float cgc[125];
  __shared__ float cre[125];
  __shared__ float wsum[4];
  __shared__ float snrm;
  int tid = threadIdx.x;

  for (int e = tid; e < n; e += blockDim.x) {
    int i  = e/(d2*d3);
    int k  = (e/d3)%d2;
    int nn = e%d3;
    cgc[e] = su2cg_f(l1, i-l1, l2, k-l2, l3, nn-l3);
  }
  __syncthreads();

  for (int e = tid; e < n; e += blockDim.x) {
    int j = e/(d2*d3);
    int l = (e/d3)%d2;
    int m = e%d3;
    float acc = 0.0f;
    for (int i = 0; i < d1; ++i) {
      for (int k = 0; k < d2; ++k) {
        int nn = (i-l1) + (k-l2) + l3;
        if (nn < 0 || nn >= d3) continue;
        float cv = cgc[(i*d2+k)*d3+nn];
        if (cv == 0.0f) continue;
        float q1r,q1i,q2r,q2i,q3r,q3i;
        qent_f(l1, i,  j, &q1r, &q1i);
        if (q1r == 0.0f && q1i == 0.0f) continue;
        qent_f(l2, k,  l, &q2r, &q2i);
        if (q2r == 0.0f && q2i == 0.0f) continue;
        qent_f(l3, nn, m, &q3r, &q3i);
        float tr = q1r*q2r - q1i*q2i;
        float ti = q1r*q2i + q1i*q2r;
        acc += cv * (tr*q3r + ti*q3i);
      }
    }
    cre[e] = acc;
  }
  __syncthreads();

  {
    float v = 0.0f;
    for (int e = tid; e < n; e += blockDim.x) v += cre[e]*cre[e];
    #pragma unroll
    for (int off = 16; off > 0; off >>= 1)
      v += __shfl_down_sync(0xffffffffu, v, off);
    if ((tid & 31) == 0) wsum[tid >> 5] = v;
    __syncthreads();
    if (tid == 0) snrm = rsqrtf(wsum[0] + wsum[1] + wsum[2] + wsum[3]);
    __syncthreads();
  }

  float scale = snrm * TALPHA[t];
  for (int e = tid; e < NE; e += blockDim.x) {
    if (ENT_T[e] != t) continue;
    int idx = ((int)ENT_I[e]*d2 + (int)ENT_J[e])*d3 + (int)ENT_K[e];
    cg_coef[e] = cre[idx] * scale;
  }
}

// ---------------------------------------------------------------------------
// Main kernel: 256 threads = 8 warps; warp w serves 32 channels of row
// z0 + (w>>2). Warp-private float4 staging, only __syncwarp in data path.
// Staging buffer declared as float4 (16B-aligned by type).
// ---------------------------------------------------------------------------
__global__ __launch_bounds__(256)
void tp_kernel(const float* __restrict__ X1, const float* __restrict__ X2,
               const float* __restrict__ W, float* __restrict__ OUT, int Z)
{
  __shared__ float g[NE];
  __shared__ float4 buf[8][72];     // per-warp slice, 72 float4 = 288 floats

  int tid = threadIdx.x;
  if (tid < NE) g[tid] = cg_coef[tid];
  __syncthreads();                  // the only block barrier

  int wid  = tid >> 5;
  int lane = tid & 31;
  int row  = blockIdx.x * 2 + (wid >> 2);
  int q    = wid & 3;               // 32-channel sub-block within the row
  int u    = q * 32 + lane;
  if (row >= Z) return;

  float4* sb4 = buf[wid];
  float*  sb  = (float*)sb4;

  // ---- stage x1 slice: global float4 -> warp-private smem ----
  {
    const float4* __restrict__ src = (const float4*)(X1 + (size_t)row * 1152);
    // l0 chunk: f4 [8q, 8q+8)          -> smem f4 [0,8)
    // l1 chunk: f4 [32+24q, +24)       -> smem f4 [8,32)
    // l2 chunk: f4 [128+40q, +40)      -> smem f4 [32,72)
    if (lane < 8)  sb4[lane]      = src[8*q + lane];
    if (lane < 24) sb4[8 + lane]  = src[32 + 24*q + lane];
    sb4[32 + lane] = src[128 + 40*q + lane];
    if (lane < 8)  sb4[64 + lane] = src[128 + 40*q + 32 + lane];
  }

  // weights for this channel (L2-resident, stride-1 across warp)
  float wv0  = W[          u];
  float wv1  = W[ 128 +    u];
  float wv2  = W[ 256 +    u];
  float wv3  = W[ 384 +    u];
  float wv4  = W[ 512 +    u];
  float wv5  = W[ 640 +    u];
  float wv6  = W[ 768 +    u];
  float wv7  = W[ 896 +    u];
  float wv8  = W[1024 +    u];
  float wv9  = W[1152 +    u];
  float wv10 = W[1280 +    u];

  // x2 components (warp-uniform)
  const float* __restrict__ yr = X2 + (size_t)row * 9;
  float y0 = yr[0], y1 = yr[1], y2 = yr[2], y3 = yr[3], y4 = yr[4];
  float y5 = yr[5], y6 = yr[6], y7 = yr[7], y8 = yr[8];

  __syncwarp();

  // ---- gather per-channel x1 components (conflict-free strided LDS) ----
  float xx0 = sb[lane];
  float xx1 = sb[32 + 3*lane    ];
  float xx2 = sb[32 + 3*lane + 1];
  float xx3 = sb[32 + 3*lane + 2];
  float xx4 = sb[128 + 5*lane    ];
  float xx5 = sb[128 + 5*lane + 1];
  float xx6 = sb[128 + 5*lane + 2];
  float xx7 = sb[128 + 5*lane + 3];
  float xx8 = sb[128 + 5*lane + 4];

  // precomputed weight*y products (35)
  float w0y0 = wv0*y0;
  float w1y1 = wv1*y1, w1y2 = wv1*y2, w1y3 = wv1*y3;
  float w2y4 = wv2*y4, w2y5 = wv2*y5, w2y6 = wv2*y6, w2y7 = wv2*y7, w2y8 = wv2*y8;
  float w3y0 = wv3*y0;
  float w4y1 = wv4*y1, w4y2 = wv4*y2, w4y3 = wv4*y3;
  float w5y1 = wv5*y1, w5y2 = wv5*y2, w5y3 = wv5*y3;
  float w6y4 = wv6*y4, w6y5 = wv6*y5, w6y6 = wv6*y6, w6y7 = wv6*y7, w6y8 = wv6*y8;
  float w7y0 = wv7*y0;
  float w8y1 = wv8*y1, w8y2 = wv8*y2, w8y3 = wv8*y3;
  float w9y4 = wv9*y4, w9y5 = wv9*y5, w9y6 = wv9*y6, w9y7 = wv9*y7, w9y8 = wv9*y8;
  float w10y4 = wv10*y4, w10y5 = wv10*y5, w10y6 = wv10*y6, w10y7 = wv10*y7, w10y8 = wv10*y8;

  float o0=0.f,o1=0.f,o2=0.f,o3=0.f,o4=0.f,o5=0.f,o6=0.f,o7=0.f,o8=0.f;

#define ACC(e,t,i,j,k) o##k = fmaf(g[e]*xx##i, w##t##y##j, o##k);
  ACC(0,0, 0,0,0)
  ACC(1,1, 0,1,1)  ACC(2,1, 0,2,2)  ACC(3,1, 0,3,3)
  ACC(4,2, 0,4,4)  ACC(5,2, 0,5,5)  ACC(6,2, 0,6,6)  ACC(7,2, 0,7,7)  ACC(8,2, 0,8,8)
  ACC(9,3, 1,0,1)  ACC(10,3, 2,0,2)  ACC(11,3, 3,0,3)
  ACC(12,4, 1,1,0) ACC(13,4, 2,2,0)  ACC(14,4, 3,3,0)
  ACC(15,5, 2,2,6) ACC(16,5, 2,3,7) ACC(17,5, 2,1,5) ACC(18,5, 3,2,7)
  ACC(19,5, 1,2,5) ACC(20,5, 3,3,6) ACC(21,5, 1,1,6) ACC(22,5, 3,3,8)
  ACC(23,5, 1,1,8) ACC(24,5, 3,1,4) ACC(25,5, 1,3,4)
  ACC(26,6, 2,6,2) ACC(27,6, 2,7,3) ACC(28,6, 2,5,1) ACC(29,6, 3,6,3)
  ACC(30,6, 1,6,1) ACC(31,6, 3,7,2) ACC(32,6, 1,5,2) ACC(33,6, 3,8,3)
  ACC(34,6, 1,8,1) ACC(35,6, 3,4,1) ACC(36,6, 1,4,3)
  ACC(37,7, 4,0,4) ACC(38,7, 5,0,5) ACC(39,7, 6,0,6) ACC(40,7, 7,0,7) ACC(41,7, 8,0,8)
  ACC(42,8, 6,2,2) ACC(43,8, 6,3,3) ACC(44,8, 6,1,1) ACC(45,8, 7,2,3)
  ACC(46,8, 5,2,1) ACC(47,8, 7,3,2) ACC(48,8, 5,1,2) ACC(49,8, 8,3,3)
  ACC(50,8, 8,1,1) ACC(51,8, 4,3,1) ACC(52,8, 4,1,3)
  ACC(53,9, 4,4,0) ACC(54,9, 5,5,0) ACC(55,9, 6,6,0) ACC(56,9, 7,7,0) ACC(57,9, 8,8,0)
  ACC(58,10, 6,6,6) ACC(59,10, 6,7,7) ACC(60,10, 6,5,5) ACC(61,10, 7,6,7)
  ACC(62,10, 5,6,5) ACC(63,10, 6,8,8) ACC(64,10, 6,4,4) ACC(65,10, 8,6,8)
  ACC(66,10, 4,6,4) ACC(67,10, 7,7,6) ACC(68,10, 5,5,6) ACC(69,10, 7,7,8)
  ACC(70,10, 5,5,8) ACC(71,10, 7,5,4) ACC(72,10, 5,7,4) ACC(73,10, 7,8,7)
  ACC(74,10, 5,8,5) ACC(75,10, 7,4,5) ACC(76,10, 5,4,7) ACC(77,10, 8,7,7)
  ACC(78,10, 4,7,5) ACC(79,10, 8,5,5) ACC(80,10, 4,5,7) ACC(81,10, 8,8,6)
  ACC(82,10, 4,4,6)
#undef ACC

  // ---- scatter results into warp-private smem (same slots) ----
  sb[lane]             = o0;
  sb[32 + 3*lane    ]  = o1;
  sb[32 + 3*lane + 1]  = o2;
  sb[32 + 3*lane + 2]  = o3;
  sb[128 + 5*lane    ] = o4;
  sb[128 + 5*lane + 1] = o5;
  sb[128 + 5*lane + 2] = o6;
  sb[128 + 5*lane + 3] = o7;
  sb[128 + 5*lane + 4] = o8;
  __syncwarp();

  // ---- drain: smem float4 -> global float4 ----
  {
    float4* __restrict__ dst = (float4*)(OUT + (size_t)row * 1152);
    if (lane < 8)  dst[8*q + lane]             = sb4[lane];
    if (lane < 24) dst[32 + 24*q + lane]       = sb4[8 + lane];
    dst[128 + 40*q + lane]                     = sb4[32 + lane];
    if (lane < 8)  dst[128 + 40*q + 32 + lane] = sb4[64 + lane];
  }
}

// ---------------------------------------------------------------------------
extern "C" void kernel_launch(void* const* d_in, const int* in_sizes, int n_in,
                              void* d_out, int out_size)
{
  const float* x1 = (const float*)d_in[0];
  const float* x2 = (const float*)d_in[1];
  const float* w  = (const float*)d_in[2];
  if (n_in >= 3) {
    int iw = -1, imax = -1;
    long long smax = -1;
    for (int i = 0; i < 3; ++i) {
      if (in_sizes[i] == 1408) iw = i;
      if ((long long)in_sizes[i] > smax) { smax = in_sizes[i]; imax = i; }
    }
    if (iw >= 0 && imax >= 0 && iw != imax) {
      int ix2 = 3 - iw - imax;
      x1 = (const float*)d_in[imax];
      x2 = (const float*)d_in[ix2];
      w  = (const float*)d_in[iw];
    }
  }

  int Z = in_sizes[0] > in_sizes[1]
            ? (in_sizes[0] > in_sizes[2] ? in_sizes[0] : in_sizes[2])
            : (in_sizes[1] > in_sizes[2] ? in_sizes[1] : in_sizes[2]);
  Z /= 1152;

  init_cg_kernel<<<NT, 128>>>();
  int grid = (Z + 1) / 2;
  tp_kernel<<<grid, 256>>>(x1, x2, w, (float*)d_out, Z);
}

// round 6
// speedup vs baseline: 2.0591x; 1.6381x over previous
#include <cuda_runtime.h>
#include <math.h>

// ============================================================================
// Sparse e3nn tensor product, uvu mode.
// irreps1 = 128x0e+128x1o+128x2e (x1: [Z,1152]), irreps2 = 1x0e+1x1o+1x2e.
// 83-entry hardcoded sparsity pattern. Coefficient VALUES are computed on the
// HOST (fp64 port of reference su2_cg + real basis transform) and passed as a
// by-value kernel parameter (constant bank). Main kernel: warp-private
// double-buffered cp.async pipeline, 4 rows per warp, no block barriers.
// ============================================================================

#define NE 83
#define NT 11

struct Coefs { float c[NE]; };

// ---------------- host-side tables (sparsity pattern) ----------------------
static const int hTL1[NT] = {0,0,0,1,1,1,1,2,2,2,2};
static const int hTL2[NT] = {0,1,2,0,1,1,2,0,1,2,2};
static const int hTL3[NT] = {0,1,2,1,0,2,1,2,1,0,2};
static const double hTALPHA[NT] = {
  0.5773502691896258, 0.8660254037844386, 1.1180339887498949,
  0.8660254037844386, 0.5773502691896258, 1.1180339887498949,
  0.8660254037844386, 1.1180339887498949, 0.8660254037844386,
  0.5773502691896258, 1.1180339887498949};

static const unsigned char hENT_T[NE] = {
  0, 1,1,1, 2,2,2,2,2, 3,3,3, 4,4,4,
  5,5,5,5,5,5,5,5,5,5,5,
  6,6,6,6,6,6,6,6,6,6,6,
  7,7,7,7,7,
  8,8,8,8,8,8,8,8,8,8,8,
  9,9,9,9,9,
  10,10,10,10,10,10,10,10,10,10,10,10,10,10,10,10,10,10,10,10,10,10,10,10,10};
static const unsigned char hENT_I[NE] = {
  0, 0,0,0, 0,0,0,0,0, 0,1,2, 0,1,2,
  1,1,1,2,0,2,0,2,0,2,0,
  1,1,1,2,0,2,0,2,0,2,0,
  0,1,2,3,4,
  2,2,2,3,1,3,1,4,4,0,0,
  0,1,2,3,4,
  2,2,2,3,1,2,2,4,0,3,1,3,1,3,1,3,1,3,1,4,0,4,0,4,0};
static const unsigned char hENT_J[NE] = {
  0, 0,1,2, 0,1,2,3,4, 0,0,0, 0,1,2,
  1,2,0,1,1,2,0,2,0,0,2,
  2,3,1,2,2,3,1,4,4,0,0,
  0,0,0,0,0,
  1,2,0,1,1,2,0,2,0,2,0,
  0,1,2,3,4,
  2,3,1,2,2,4,0,2,2,3,1,3,1,1,3,4,4,0,0,3,3,1,1,4,0};
static const unsigned char hENT_K[NE] = {
  0, 0,1,2, 0,1,2,3,4, 0,1,2, 0,0,0,
  2,3,1,3,1,2,2,4,4,0,0,
  1,2,0,2,0,1,1,2,0,0,2,
  0,1,2,3,4,
  1,2,0,2,0,1,1,2,0,0,2,
  0,0,0,0,0,
  2,3,1,3,1,4,0,4,0,2,2,4,4,0,0,3,1,1,3,3,1,1,3,2,2};

// ---------------- host coefficient computation (fp64) ----------------------
static double hfact(int n) {
  double r = 1.0;
  for (int i = 2; i <= n; ++i) r *= (double)i;
  return r;
}

static double hsu2cg(int j1,int m1,int j2,int m2,int j3,int m3) {
  if (m1 + m2 != m3) return 0.0;
  int vmin = -j1+j2+m3; if (-j1+m1 > vmin) vmin = -j1+m1; if (vmin < 0) vmin = 0;
  int vmax = j2+j3+m1; if (j3-j1+j2 < vmax) vmax = j3-j1+j2; if (j3+m3 < vmax) vmax = j3+m3;
  double C = sqrt((2.0*j3+1.0)*hfact(j3+j1-j2)*hfact(j3-j1+j2)*hfact(j1+j2-j3)
                  *hfact(j3+m3)*hfact(j3-m3)
                  /(hfact(j1+j2+j3+1)*hfact(j1-m1)*hfact(j1+m1)*hfact(j2-m2)*hfact(j2+m2)));
  double S = 0.0;
  for (int v = vmin; v <= vmax; ++v) {
    double s = ((v + j2 + m2) & 1) ? -1.0 : 1.0;
    S += s * hfact(j2+j3+m1-v)*hfact(j1-m1+v)
         /(hfact(v)*hfact(j3-j1+j2-v)*hfact(j3+m3-v)*hfact(v+j1-j2-m3));
  }
  return C * S;
}

static void hqent(int l, int r, int c, double* qr, double* qi) {
  const double inv2 = 0.7071067811865476;
  double re = 0.0, im = 0.0;
  int m = r - l;
  if (m < 0) {
    if (c == l - m) re = inv2;
    if (c == l + m) im = -inv2;
  } else if (m == 0) {
    if (c == l) re = 1.0;
  } else {
    double s = (m & 1) ? -1.0 : 1.0;
    if (c == l + m) re = s * inv2;
    if (c == l - m) im = s * inv2;
  }
  if (l == 1) { double t0 = re; re = im; im = -t0; }
  else if (l == 2) { re = -re; im = -im; }
  *qr = re; *qi = im;
}

static void compute_coefs(Coefs* out) {
  for (int t = 0; t < NT; ++t) {
    int l1 = hTL1[t], l2 = hTL2[t], l3 = hTL3[t];
    int d1 = 2*l1+1, d2 = 2*l2+1, d3 = 2*l3+1;
    double cgc[125], cre[125];
    for (int i = 0; i < d1; ++i)
      for (int k = 0; k < d2; ++k)
        for (int nn = 0; nn < d3; ++nn)
          cgc[(i*d2+k)*d3+nn] = hsu2cg(l1, i-l1, l2, k-l2, l3, nn-l3);
    double nrm = 0.0;
    for (int j = 0; j < d1; ++j)
      for (int l = 0; l < d2; ++l)
        for (int m = 0; m < d3; ++m) {
          double acc = 0.0;
          for (int i = 0; i < d1; ++i)
            for (int k = 0; k < d2; ++k) {
              int nn = (i-l1) + (k-l2) + l3;
              if (nn < 0 || nn >= d3) continue;
              double cv = cgc[(i*d2+k)*d3+nn];
              if (cv == 0.0) continue;
              double q1r,q1i,q2r,q2i,q3r,q3i;
              hqent(l1, i,  j, &q1r, &q1i);
              if (q1r == 0.0 && q1i == 0.0) continue;
              hqent(l2, k,  l, &q2r, &q2i);
              if (q2r == 0.0 && q2i == 0.0) continue;
              hqent(l3, nn, m, &q3r, &q3i);
              double tr = q1r*q2r - q1i*q2i;
              double ti = q1r*q2i + q1i*q2r;
              acc += cv * (tr*q3r + ti*q3i);
            }
          cre[(j*d2+l)*d3+m] = acc;
          nrm += acc*acc;
        }
    double scale = hTALPHA[t] / sqrt(nrm);
    for (int e = 0; e < NE; ++e) {
      if (hENT_T[e] != t) continue;
      int idx = ((int)hENT_I[e]*d2 + (int)hENT_J[e])*d3 + (int)hENT_K[e];
      out->c[e] = (float)(cre[idx] * scale);
    }
  }
}

// ---------------------------------------------------------------------------
// Device kernel
// ---------------------------------------------------------------------------
#define CPA16(dst, src) \
  asm volatile("cp.async.cg.shared.global [%0], [%1], 16;" :: \
               "r"((unsigned)__cvta_generic_to_shared(dst)), "l"(src))

__device__ __forceinline__ void issue_slice(float4* sb4, const float4* src,
                                            int q, int lane) {
  if (lane < 8)  CPA16(sb4 + lane,      src + 8*q + lane);
  if (lane < 24) CPA16(sb4 + 8 + lane,  src + 32 + 24*q + lane);
  CPA16(sb4 + 32 + lane, src + 128 + 40*q + lane);
  if (lane < 8)  CPA16(sb4 + 64 + lane, src + 128 + 40*q + 32 + lane);
}

__global__ __launch_bounds__(256)
void tp_kernel(const float* __restrict__ X1, const float* __restrict__ X2,
               const float* __restrict__ W, float* __restrict__ OUT, int Z,
               Coefs coef)
{
  __shared__ float4 buf[8][2][72];   // [warp][double buffer][72 float4]

  int tid  = threadIdx.x;
  int wid  = tid >> 5;
  int lane = tid & 31;
  int q    = wid & 3;                // 32-channel quarter of the row
  int slot = wid >> 2;               // 0/1: row parity within block
  int base = blockIdx.x * 8 + slot;  // rows: base, base+2, base+4, base+6
  int u    = q * 32 + lane;

  // hoisted weights (amortized over 4 rows)
  float wv0  = W[          u];
  float wv1  = W[ 128 +    u];
  float wv2  = W[ 256 +    u];
  float wv3  = W[ 384 +    u];
  float wv4  = W[ 512 +    u];
  float wv5  = W[ 640 +    u];
  float wv6  = W[ 768 +    u];
  float wv7  = W[ 896 +    u];
  float wv8  = W[1024 +    u];
  float wv9  = W[1152 +    u];
  float wv10 = W[1280 +    u];

  float4* b[2] = { buf[wid][0], buf[wid][1] };

  // prologue: stage first row slice + its x2
  float yv[9];
  if (base < Z) {
    issue_slice(b[0], (const float4*)(X1 + (size_t)base * 1152), q, lane);
    const float* yr = X2 + (size_t)base * 9;
    #pragma unroll
    for (int i = 0; i < 9; ++i) yv[i] = yr[i];
  } else {
    #pragma unroll
    for (int i = 0; i < 9; ++i) yv[i] = 0.0f;
  }
  asm volatile("cp.async.commit_group;");

  #pragma unroll
  for (int it = 0; it < 4; ++it) {
    int row = base + 2*it;
    float4* cur = b[it & 1];
    float*  sb  = (float*)cur;

    float yn[9];
    if (it < 3) {
      int nr = base + 2*(it+1);
      if (nr < Z) {
        issue_slice(b[(it+1) & 1], (const float4*)(X1 + (size_t)nr * 1152), q, lane);
        const float* yr = X2 + (size_t)nr * 9;
        #pragma unroll
        for (int i = 0; i < 9; ++i) yn[i] = yr[i];
      } else {
        #pragma unroll
        for (int i = 0; i < 9; ++i) yn[i] = 0.0f;
      }
    }
    asm volatile("cp.async.commit_group;");
    if (it < 3) asm volatile("cp.async.wait_group 1;");
    else        asm volatile("cp.async.wait_group 0;");
    __syncwarp();

    if (row < Z) {
      // gather per-channel x1 components (conflict-free strided LDS)
      float xx0 = sb[lane];
      float xx1 = sb[32 + 3*lane    ];
      float xx2 = sb[32 + 3*lane + 1];
      float xx3 = sb[32 + 3*lane + 2];
      float xx4 = sb[128 + 5*lane    ];
      float xx5 = sb[128 + 5*lane + 1];
      float xx6 = sb[128 + 5*lane + 2];
      float xx7 = sb[128 + 5*lane + 3];
      float xx8 = sb[128 + 5*lane + 4];

      float o0=0.f,o1=0.f,o2=0.f,o3=0.f,o4=0.f,o5=0.f,o6=0.f,o7=0.f,o8=0.f;

#define CF(e) coef.c[e]
#define ACC(e,i,WY,k) o##k = fmaf(CF(e)*xx##i, WY, o##k);
      { // t0: 0e x 0e -> 0e
        float a0 = wv0*yv[0];
        ACC(0, 0, a0, 0)
      }
      { // t1: 0e x 1o -> 1o
        float a1 = wv1*yv[1], a2 = wv1*yv[2], a3 = wv1*yv[3];
        ACC(1, 0, a1, 1)  ACC(2, 0, a2, 2)  ACC(3, 0, a3, 3)
      }
      { // t2: 0e x 2e -> 2e
        float a4 = wv2*yv[4], a5 = wv2*yv[5], a6 = wv2*yv[6], a7 = wv2*yv[7], a8 = wv2*yv[8];
        ACC(4, 0, a4, 4)  ACC(5, 0, a5, 5)  ACC(6, 0, a6, 6)  ACC(7, 0, a7, 7)  ACC(8, 0, a8, 8)
      }
      { // t3: 1o x 0e -> 1o
        float a0 = wv3*yv[0];
        ACC(9, 1, a0, 1)  ACC(10, 2, a0, 2)  ACC(11, 3, a0, 3)
      }
      { // t4: 1o x 1o -> 0e
        float a1 = wv4*yv[1], a2 = wv4*yv[2], a3 = wv4*yv[3];
        ACC(12, 1, a1, 0) ACC(13, 2, a2, 0) ACC(14, 3, a3, 0)
      }
      { // t5: 1o x 1o -> 2e
        float a1 = wv5*yv[1], a2 = wv5*yv[2], a3 = wv5*yv[3];
        ACC(15, 2, a2, 6) ACC(16, 2, a3, 7) ACC(17, 2, a1, 5) ACC(18, 3, a2, 7)
        ACC(19, 1, a2, 5) ACC(20, 3, a3, 6) ACC(21, 1, a1, 6) ACC(22, 3, a3, 8)
        ACC(23, 1, a1, 8) ACC(24, 3, a1, 4) ACC(25, 1, a3, 4)
      }
      { // t6: 1o x 2e -> 1o
        float a4 = wv6*yv[4], a5 = wv6*yv[5], a6 = wv6*yv[6], a7 = wv6*yv[7], a8 = wv6*yv[8];
        ACC(26, 2, a6, 2) ACC(27, 2, a7, 3) ACC(28, 2, a5, 1) ACC(29, 3, a6, 3)
        ACC(30, 1, a6, 1) ACC(31, 3, a7, 2) ACC(32, 1, a5, 2) ACC(33, 3, a8, 3)
        ACC(34, 1, a8, 1) ACC(35, 3, a4, 1) ACC(36, 1, a4, 3)
      }
      { // t7: 2e x 0e -> 2e
        float a0 = wv7*yv[0];
        ACC(37, 4, a0, 4) ACC(38, 5, a0, 5) ACC(39, 6, a0, 6) ACC(40, 7, a0, 7) ACC(41, 8, a0, 8)
      }
      { // t8: 2e x 1o -> 1o
        float a1 = wv8*yv[1], a2 = wv8*yv[2], a3 = wv8*yv[3];
        ACC(42, 6, a2, 2) ACC(43, 6, a3, 3) ACC(44, 6, a1, 1) ACC(45, 7, a2, 3)
        ACC(46, 5, a2, 1) ACC(47, 7, a3, 2) ACC(48, 5, a1, 2) ACC(49, 8, a3, 3)
        ACC(50, 8, a1, 1) ACC(51, 4, a3, 1) ACC(52, 4, a1, 3)
      }
      { // t9: 2e x 2e -> 0e
        float a4 = wv9*yv[4], a5 = wv9*yv[5], a6 = wv9*yv[6], a7 = wv9*yv[7], a8 = wv9*yv[8];
        ACC(53, 4, a4, 0) ACC(54, 5, a5, 0) ACC(55, 6, a6, 0) ACC(56, 7, a7, 0) ACC(57, 8, a8, 0)
      }
      { // t10: 2e x 2e -> 2e
        float a4 = wv10*yv[4], a5 = wv10*yv[5], a6 = wv10*yv[6], a7 = wv10*yv[7], a8 = wv10*yv[8];
        ACC(58, 6, a6, 6) ACC(59, 6, a7, 7) ACC(60, 6, a5, 5) ACC(61, 7, a6, 7)
        ACC(62, 5, a6, 5) ACC(63, 6, a8, 8) ACC(64, 6, a4, 4) ACC(65, 8, a6, 8)
        ACC(66, 4, a6, 4) ACC(67, 7, a7, 6) ACC(68, 5, a5, 6) ACC(69, 7, a7, 8)
        ACC(70, 5, a5, 8) ACC(71, 7, a5, 4) ACC(72, 5, a7, 4) ACC(73, 7, a8, 7)
        ACC(74, 5, a8, 5) ACC(75, 7, a4, 5) ACC(76, 5, a4, 7) ACC(77, 8, a7, 7)
        ACC(78, 4, a7, 5) ACC(79, 8, a5, 5) ACC(80, 4, a5, 7) ACC(81, 8, a8, 6)
        ACC(82, 4, a4, 6)
      }
#undef ACC
#undef CF

      // scatter outputs into the same warp-private buffer
      sb[lane]             = o0;
      sb[32 + 3*lane    ]  = o1;
      sb[32 + 3*lane + 1]  = o2;
      sb[32 + 3*lane + 2]  = o3;
      sb[128 + 5*lane    ] = o4;
      sb[128 + 5*lane + 1] = o5;
      sb[128 + 5*lane + 2] = o6;
      sb[128 + 5*lane + 3] = o7;
      sb[128 + 5*lane + 4] = o8;
      __syncwarp();

      // drain: smem float4 -> global float4
      float4* __restrict__ dst = (float4*)(OUT + (size_t)row * 1152);
      if (lane < 8)  dst[8*q + lane]             = cur[lane];
      if (lane < 24) dst[32 + 24*q + lane]       = cur[8 + lane];
      dst[128 + 40*q + lane]                     = cur[32 + lane];
      if (lane < 8)  dst[128 + 40*q + 32 + lane] = cur[64 + lane];
    }
    __syncwarp();   // all lanes done reading cur before next cp.async overwrites

    if (it < 3) {
      #pragma unroll
      for (int i = 0; i < 9; ++i) yv[i] = yn[i];
    }
  }
}

// ---------------------------------------------------------------------------
extern "C" void kernel_launch(void* const* d_in, const int* in_sizes, int n_in,
                              void* d_out, int out_size)
{
  const float* x1 = (const float*)d_in[0];
  const float* x2 = (const float*)d_in[1];
  const float* w  = (const float*)d_in[2];
  if (n_in >= 3) {
    int iw = -1, imax = -1;
    long long smax = -1;
    for (int i = 0; i < 3; ++i) {
      if (in_sizes[i] == 1408) iw = i;
      if ((long long)in_sizes[i] > smax) { smax = in_sizes[i]; imax = i; }
    }
    if (iw >= 0 && imax >= 0 && iw != imax) {
      int ix2 = 3 - iw - imax;
      x1 = (const float*)d_in[imax];
      x2 = (const float*)d_in[ix2];
      w  = (const float*)d_in[iw];
    }
  }

  int Z = in_sizes[0] > in_sizes[1]
            ? (in_sizes[0] > in_sizes[2] ? in_sizes[0] : in_sizes[2])
            : (in_sizes[1] > in_sizes[2] ? in_sizes[1] : in_sizes[2]);
  Z /= 1152;

  Coefs coef;
  compute_coefs(&coef);

  int grid = (Z + 7) / 8;
  tp_kernel<<<grid, 256>>>(x1, x2, w, (float*)d_out, Z, coef);
}